// round 6
// baseline (speedup 1.0000x reference)
#include <cuda_runtime.h>
#include <cuda_fp16.h>
#include <cstdint>

// ---------------- problem dims ----------------
#define T_TOK 8192
#define D_DIM 1024
#define H_DIM 2048
#define O_DIM 1024
#define N_EXP 8
#define SLOTS 16384   // T_TOK * 2
#define CAPE  8192    // max rows per expert

// ---------------- scratch (device globals; no allocation allowed) ----------------
__device__ __half g_xh[(size_t)T_TOK * D_DIM];            // x in fp16
__device__ __half g_w1t[(size_t)N_EXP * H_DIM * D_DIM];   // w1^T  [E][H][D]
__device__ __half g_w2t[(size_t)N_EXP * O_DIM * H_DIM];   // w2^T  [E][O][H]
__device__ __half g_h[(size_t)SLOTS * H_DIM];             // hidden per slot
__device__ float  g_part[(size_t)SLOTS * O_DIM];          // partial out per slot
__device__ int    g_list[N_EXP * CAPE];                   // slot ids per expert
__device__ float  g_gval[SLOTS];                          // gate value per slot
__device__ int    g_cnt[N_EXP];

// ---------------- helpers ----------------
__device__ __forceinline__ uint32_t smem_u32(const void* p) {
    uint32_t a;
    asm("{ .reg .u64 t; cvta.to.shared.u64 t, %1; cvt.u32.u64 %0, t; }" : "=r"(a) : "l"(p));
    return a;
}
#define CP16(d, s, sz) \
    asm volatile("cp.async.cg.shared.global [%0], [%1], 16, %2;" :: "r"(d), "l"(s), "r"(sz))
#define CP_COMMIT() asm volatile("cp.async.commit_group;")
#define CP_WAIT2()  asm volatile("cp.async.wait_group 2;")
#define LDMX4(r0, r1, r2, r3, addr)                                            \
    asm volatile("ldmatrix.sync.aligned.m8n8.x4.shared.b16 {%0,%1,%2,%3}, [%4];" \
        : "=r"(r0), "=r"(r1), "=r"(r2), "=r"(r3) : "r"(addr))
#define MMA16816(d, a0, a1, a2, a3, b0, b1)                                    \
    asm volatile("mma.sync.aligned.m16n8k16.row.col.f32.f16.f16.f32 "          \
        "{%0,%1,%2,%3}, {%4,%5,%6,%7}, {%8,%9}, {%0,%1,%2,%3};"                \
        : "+f"((d)[0]), "+f"((d)[1]), "+f"((d)[2]), "+f"((d)[3])               \
        : "r"(a0), "r"(a1), "r"(a2), "r"(a3), "r"(b0), "r"(b1))

// smem tile layout: per stage A[128][40 halfs] (80B rows) + B[128][40]
#define ROW_B 80
#define A_BYTES (128 * ROW_B)          // 10240
#define STAGE_BYTES (2 * A_BYTES)      // 20480
#define NSTAGE 4
#define SMEM_GEMM (NSTAGE * STAGE_BYTES + 512 + 512)   // tiles + slots + bias = 82944

// ---------------- kernel 0: zero counts ----------------
__global__ void zero_cnt_kernel() {
    if (threadIdx.x < N_EXP) g_cnt[threadIdx.x] = 0;
}

// ---------------- kernel 1: gate + x->fp16 ----------------
__global__ void __launch_bounds__(256) gate_kernel(const float* __restrict__ x,
                                                   const float* __restrict__ gw,
                                                   const float* __restrict__ gb) {
    const int warp = threadIdx.x >> 5, lane = threadIdx.x & 31;
    const int t = blockIdx.x * 8 + warp;
    const float* xr = x + (size_t)t * D_DIM;
    float acc[N_EXP];
#pragma unroll
    for (int e = 0; e < N_EXP; e++) acc[e] = 0.f;
    for (int d = lane; d < D_DIM; d += 32) {
        float xv = xr[d];
        g_xh[(size_t)t * D_DIM + d] = __float2half_rn(xv);
#pragma unroll
        for (int e = 0; e < N_EXP; e++) acc[e] += xv * __ldg(&gw[e * D_DIM + d]);
    }
#pragma unroll
    for (int e = 0; e < N_EXP; e++) {
#pragma unroll
        for (int o = 16; o > 0; o >>= 1) acc[e] += __shfl_xor_sync(0xffffffffu, acc[e], o);
    }
    if (lane == 0) {
        float lg[N_EXP], m = -1e30f;
#pragma unroll
        for (int e = 0; e < N_EXP; e++) { lg[e] = acc[e] + gb[e]; m = fmaxf(m, lg[e]); }
        float p[N_EXP], s = 0.f;
#pragma unroll
        for (int e = 0; e < N_EXP; e++) { p[e] = expf(lg[e] - m); s += p[e]; }
        int i1 = 0;
#pragma unroll
        for (int e = 1; e < N_EXP; e++) if (p[e] > p[i1]) i1 = e;
        int i2 = (i1 == 0) ? 1 : 0;
#pragma unroll
        for (int e = 0; e < N_EXP; e++) if (e != i1 && p[e] > p[i2]) i2 = e;
        float inv = 1.f / s;
        g_gval[2 * t]     = p[i1] * inv;
        g_gval[2 * t + 1] = p[i2] * inv;
        int q1 = atomicAdd(&g_cnt[i1], 1); g_list[i1 * CAPE + q1] = 2 * t;
        int q2 = atomicAdd(&g_cnt[i2], 1); g_list[i2 * CAPE + q2] = 2 * t + 1;
    }
}

// ---------------- kernel 2: weight transpose + fp16 convert ----------------
// in: [E][R][C] fp32 -> out: [E][C][R] fp16
__global__ void transpose_w_kernel(const float* __restrict__ in, int R, int C, int which) {
    __shared__ float tile[32][33];
    const int e = blockIdx.z;
    const size_t base = (size_t)e * R * C;
    const int c0 = blockIdx.x * 32, r0 = blockIdx.y * 32;
    const int tx = threadIdx.x, ty = threadIdx.y;
#pragma unroll
    for (int i = 0; i < 32; i += 8)
        tile[ty + i][tx] = in[base + (size_t)(r0 + ty + i) * C + c0 + tx];
    __syncthreads();
    __half* out = which ? g_w2t : g_w1t;
#pragma unroll
    for (int i = 0; i < 32; i += 8)
        out[base + (size_t)(c0 + ty + i) * R + r0 + tx] = __float2half_rn(tile[tx][ty + i]);
}

// ---------------- grouped GEMM (WHICH=1: x@w1 +b1, relu -> g_h fp16)
// ----------------              (WHICH=2: h@w2 +b2, *gate -> g_part fp32)
template <int WHICH>
__global__ void __launch_bounds__(256, 2) moe_gemm_kernel(const float* __restrict__ bias) {
    constexpr int KDIM = (WHICH == 1) ? D_DIM : H_DIM;
    constexpr int NDIM = (WHICH == 1) ? H_DIM : O_DIM;
    constexpr int KT = KDIM / 32;

    const int e = blockIdx.z;
    const int ne = g_cnt[e];
    const int mbase = blockIdx.x * 128;
    if (mbase >= ne) return;
    const int nbase = blockIdx.y * 128;

    extern __shared__ char smem[];
    const uint32_t sb = smem_u32(smem);
    int*   slotsS = (int*)(smem + NSTAGE * STAGE_BYTES);
    float* biasS  = (float*)(smem + NSTAGE * STAGE_BYTES + 512);

    const int tid = threadIdx.x, lane = tid & 31, wid = tid >> 5;
    const int warp_m = wid >> 2, warp_n = wid & 3;

    if (tid < 128) {
        int grow = mbase + tid;
        slotsS[tid] = (grow < ne) ? __ldg(&g_list[e * CAPE + grow]) : -1;
        biasS[tid]  = __ldg(&bias[(size_t)e * NDIM + nbase + tid]);
    }
    __syncthreads();

    // per-thread cp.async source/dest (one A row + one B row, 2 chunks of 16B each)
    const int lrow = tid >> 1;
    const int j0 = (tid & 1) * 2;
    const int slotL = slotsS[lrow];
    uint32_t aSz = 16;
    const char* aSrc;
    if (slotL < 0) { aSrc = (const char*)g_xh; aSz = 0; }
    else if (WHICH == 1) aSrc = (const char*)(g_xh + (size_t)(slotL >> 1) * D_DIM);
    else                 aSrc = (const char*)(g_h + (size_t)slotL * H_DIM);
    aSrc += j0 * 16;
    const __half* wsrc = (WHICH == 1) ? (g_w1t + ((size_t)e * H_DIM + nbase) * D_DIM)
                                      : (g_w2t + ((size_t)e * O_DIM + nbase) * H_DIM);
    const char* bSrc = (const char*)(wsrc + (size_t)lrow * KDIM) + j0 * 16;
    const uint32_t aDst = sb + lrow * ROW_B + j0 * 16;
    const uint32_t bDst = sb + A_BYTES + lrow * ROW_B + j0 * 16;

#define ISSUE(kt_)                                                   \
    do {                                                             \
        uint32_t s_ = ((kt_) & 3) * STAGE_BYTES;                     \
        const char* as_ = aSrc + (size_t)(kt_) * 64;                 \
        const char* bs_ = bSrc + (size_t)(kt_) * 64;                 \
        CP16(aDst + s_,      as_,      aSz);                         \
        CP16(aDst + s_ + 16, as_ + 16, aSz);                         \
        CP16(bDst + s_,      bs_,      16u);                         \
        CP16(bDst + s_ + 16, bs_ + 16, 16u);                         \
    } while (0)

    ISSUE(0); CP_COMMIT();
    ISSUE(1); CP_COMMIT();
    ISSUE(2); CP_COMMIT();

    float acc[4][4][4];
#pragma unroll
    for (int a = 0; a < 4; a++)
#pragma unroll
        for (int b = 0; b < 4; b++)
#pragma unroll
            for (int c = 0; c < 4; c++) acc[a][b][c] = 0.f;

#pragma unroll 1
    for (int kt = 0; kt < KT; kt++) {
        CP_WAIT2();
        __syncthreads();
        if (kt + 3 < KT) ISSUE(kt + 3);
        CP_COMMIT();

        const uint32_t As = sb + (kt & 3) * STAGE_BYTES;
        const uint32_t Bs = As + A_BYTES;
#pragma unroll
        for (int ks = 0; ks < 2; ks++) {
            uint32_t bfr[8];
            const int grp = lane >> 3, l8 = lane & 7;
#pragma unroll
            for (int h = 0; h < 2; h++) {
                int nrow = warp_n * 32 + h * 16 + (grp >> 1) * 8 + l8;
                int chk = ks * 2 + (grp & 1);
                uint32_t addr = Bs + nrow * ROW_B + chk * 16;
                LDMX4(bfr[h * 4 + 0], bfr[h * 4 + 1], bfr[h * 4 + 2], bfr[h * 4 + 3], addr);
            }
#pragma unroll
            for (int mi = 0; mi < 4; mi++) {
                int arow = warp_m * 64 + mi * 16 + (lane & 15);
                int achk = ks * 2 + (lane >> 4);
                uint32_t addr = As + arow * ROW_B + achk * 16;
                uint32_t a0, a1, a2, a3;
                LDMX4(a0, a1, a2, a3, addr);
#pragma unroll
                for (int ni = 0; ni < 4; ni++) {
                    MMA16816(acc[mi][ni], a0, a1, a2, a3,
                             bfr[(ni >> 1) * 4 + (ni & 1) * 2],
                             bfr[(ni >> 1) * 4 + (ni & 1) * 2 + 1]);
                }
            }
        }
    }

    // epilogue
    const int gr = lane >> 2, gc = (lane & 3) * 2;
#pragma unroll
    for (int mi = 0; mi < 4; mi++) {
#pragma unroll
        for (int rh = 0; rh < 2; rh++) {
            int lr = warp_m * 64 + mi * 16 + rh * 8 + gr;
            int slot2 = slotsS[lr];
            if (slot2 < 0) continue;
            if (WHICH == 1) {
                __half* dst = g_h + (size_t)slot2 * H_DIM + nbase;
#pragma unroll
                for (int ni = 0; ni < 4; ni++) {
                    int lc = warp_n * 32 + ni * 8 + gc;
                    float v0 = fmaxf(acc[mi][ni][rh * 2 + 0] + biasS[lc], 0.f);
                    float v1 = fmaxf(acc[mi][ni][rh * 2 + 1] + biasS[lc + 1], 0.f);
                    *(__half2*)(dst + lc) = __floats2half2_rn(v0, v1);
                }
            } else {
                float gv = __ldg(&g_gval[slot2]);
                float* dst = g_part + (size_t)slot2 * O_DIM + nbase;
#pragma unroll
                for (int ni = 0; ni < 4; ni++) {
                    int lc = warp_n * 32 + ni * 8 + gc;
                    float2 o;
                    o.x = (acc[mi][ni][rh * 2 + 0] + biasS[lc]) * gv;
                    o.y = (acc[mi][ni][rh * 2 + 1] + biasS[lc + 1]) * gv;
                    *(float2*)(dst + lc) = o;
                }
            }
        }
    }
#undef ISSUE
}

// ---------------- combine: out[t] = part[2t] + part[2t+1] ----------------
__global__ void __launch_bounds__(256) combine_kernel(float* __restrict__ out) {
    int i = blockIdx.x * 256 + threadIdx.x;   // over T_TOK * O_DIM / 4
    int t = i >> 8, q = i & 255;
    const float4 a = *((const float4*)(g_part + (size_t)(2 * t) * O_DIM) + q);
    const float4 b = *((const float4*)(g_part + (size_t)(2 * t + 1) * O_DIM) + q);
    ((float4*)(out + (size_t)t * O_DIM))[q] =
        make_float4(a.x + b.x, a.y + b.y, a.z + b.z, a.w + b.w);
}

// ---------------- launcher ----------------
extern "C" void kernel_launch(void* const* d_in, const int* in_sizes, int n_in,
                              void* d_out, int out_size) {
    const float* x  = (const float*)d_in[0];
    const float* gw = (const float*)d_in[1];
    const float* gb = (const float*)d_in[2];
    const float* w1 = (const float*)d_in[3];
    const float* b1 = (const float*)d_in[4];
    const float* w2 = (const float*)d_in[5];
    const float* b2 = (const float*)d_in[6];
    float* out = (float*)d_out;

    cudaFuncSetAttribute(moe_gemm_kernel<1>, cudaFuncAttributeMaxDynamicSharedMemorySize, SMEM_GEMM);
    cudaFuncSetAttribute(moe_gemm_kernel<2>, cudaFuncAttributeMaxDynamicSharedMemorySize, SMEM_GEMM);

    zero_cnt_kernel<<<1, 32>>>();
    gate_kernel<<<T_TOK / 8, 256>>>(x, gw, gb);
    transpose_w_kernel<<<dim3(H_DIM / 32, D_DIM / 32, N_EXP), dim3(32, 8)>>>(w1, D_DIM, H_DIM, 0);
    transpose_w_kernel<<<dim3(O_DIM / 32, H_DIM / 32, N_EXP), dim3(32, 8)>>>(w2, H_DIM, O_DIM, 1);
    moe_gemm_kernel<1><<<dim3(CAPE / 128, H_DIM / 128, N_EXP), 256, SMEM_GEMM>>>(b1);
    moe_gemm_kernel<2><<<dim3(CAPE / 128, O_DIM / 128, N_EXP), 256, SMEM_GEMM>>>(b2);
    combine_kernel<<<(T_TOK * O_DIM / 4) / 256, 256>>>(out);
}

// round 7
// speedup vs baseline: 1.0143x; 1.0143x over previous
#include <cuda_runtime.h>
#include <cuda_fp16.h>
#include <cstdint>

// ---------------- problem dims ----------------
#define T_TOK 8192
#define D_DIM 1024
#define H_DIM 2048
#define O_DIM 1024
#define N_EXP 8
#define SLOTS 16384   // T_TOK * 2
#define CAPE  8192    // max rows per expert

// ---------------- scratch (device globals; no allocation allowed) ----------------
__device__ __half g_xh[(size_t)T_TOK * D_DIM];            // x in fp16
__device__ __half g_w1t[(size_t)N_EXP * H_DIM * D_DIM];   // w1^T  [E][H][D]
__device__ __half g_w2t[(size_t)N_EXP * O_DIM * H_DIM];   // w2^T  [E][O][H]
__device__ __half g_h[(size_t)SLOTS * H_DIM];             // hidden per slot
__device__ float  g_part[(size_t)SLOTS * O_DIM];          // partial out per slot
__device__ int    g_list[N_EXP * CAPE];                   // slot ids per expert
__device__ float  g_gval[SLOTS];                          // gate value per slot
__device__ int    g_cnt[N_EXP];

// ---------------- helpers ----------------
__device__ __forceinline__ uint32_t smem_u32(const void* p) {
    uint32_t a;
    asm("{ .reg .u64 t; cvta.to.shared.u64 t, %1; cvt.u32.u64 %0, t; }" : "=r"(a) : "l"(p));
    return a;
}
#define CP16(d, s, sz) \
    asm volatile("cp.async.cg.shared.global [%0], [%1], 16, %2;" :: "r"(d), "l"(s), "r"(sz))
#define CP_COMMIT() asm volatile("cp.async.commit_group;")
#define CP_WAIT2()  asm volatile("cp.async.wait_group 2;")
#define LDMX4(r0, r1, r2, r3, addr)                                            \
    asm volatile("ldmatrix.sync.aligned.m8n8.x4.shared.b16 {%0,%1,%2,%3}, [%4];" \
        : "=r"(r0), "=r"(r1), "=r"(r2), "=r"(r3) : "r"(addr))
#define MMA16816(d, a0, a1, a2, a3, b0, b1)                                    \
    asm volatile("mma.sync.aligned.m16n8k16.row.col.f32.f16.f16.f32 "          \
        "{%0,%1,%2,%3}, {%4,%5,%6,%7}, {%8,%9}, {%0,%1,%2,%3};"                \
        : "+f"((d)[0]), "+f"((d)[1]), "+f"((d)[2]), "+f"((d)[3])               \
        : "r"(a0), "r"(a1), "r"(a2), "r"(a3), "r"(b0), "r"(b1))

// smem tile layout: per stage A[128][40 halfs] (80B rows) + B[128][40]
#define ROW_B 80
#define A_BYTES (128 * ROW_B)          // 10240
#define STAGE_BYTES (2 * A_BYTES)      // 20480
#define NSTAGE 4
#define SMEM_GEMM (NSTAGE * STAGE_BYTES + 512 + 512)   // tiles + slots + bias = 82944

// ---------------- kernel 1: weight transpose + fp16 convert (vectorized) ----------
// in: [E][R][C] fp32 -> out: [E][C][R] fp16; zflag: also zero g_cnt (block 0)
__global__ void __launch_bounds__(256) transpose_w_kernel(const float* __restrict__ in,
                                                          int R, int C, int which, int zflag) {
    __shared__ float tile[32][33];
    if (zflag && blockIdx.x == 0 && blockIdx.y == 0 && blockIdx.z == 0 && threadIdx.x < N_EXP &&
        threadIdx.y == 0)
        g_cnt[threadIdx.x] = 0;
    const int e = blockIdx.z;
    const size_t base = (size_t)e * R * C;
    const int c0 = blockIdx.x * 32, r0 = blockIdx.y * 32;
    const int tx = threadIdx.x, ty = threadIdx.y;   // blockDim = (8, 32)
    // load 32x32 fp32 tile, float4 per thread
    float4 v = *(const float4*)(in + base + (size_t)(r0 + ty) * C + c0 + 4 * tx);
    tile[ty][4 * tx + 0] = v.x;
    tile[ty][4 * tx + 1] = v.y;
    tile[ty][4 * tx + 2] = v.z;
    tile[ty][4 * tx + 3] = v.w;
    __syncthreads();
    // store transposed as fp16, 4 halves (uint2) per thread; bank = (4tx+ty)%32 pattern is conflict-free
    __half* out = which ? g_w2t : g_w1t;
    float f0 = tile[4 * tx + 0][ty];
    float f1 = tile[4 * tx + 1][ty];
    float f2 = tile[4 * tx + 2][ty];
    float f3 = tile[4 * tx + 3][ty];
    __half2 h01 = __floats2half2_rn(f0, f1);
    __half2 h23 = __floats2half2_rn(f2, f3);
    uint2 u;
    u.x = *reinterpret_cast<uint32_t*>(&h01);
    u.y = *reinterpret_cast<uint32_t*>(&h23);
    *reinterpret_cast<uint2*>(out + base + (size_t)(c0 + ty) * R + r0 + 4 * tx) = u;
}

// ---------------- kernel 2: gate + x->fp16 (vectorized) ----------------
__global__ void __launch_bounds__(256) gate_kernel(const float* __restrict__ x,
                                                   const float* __restrict__ gw,
                                                   const float* __restrict__ gb) {
    const int warp = threadIdx.x >> 5, lane = threadIdx.x & 31;
    const int t = blockIdx.x * 8 + warp;
    const float* xr = x + (size_t)t * D_DIM;
    float acc[N_EXP];
#pragma unroll
    for (int e = 0; e < N_EXP; e++) acc[e] = 0.f;
#pragma unroll 1
    for (int d = lane * 4; d < D_DIM; d += 128) {
        float4 xv = *(const float4*)(xr + d);
        __half2 h01 = __floats2half2_rn(xv.x, xv.y);
        __half2 h23 = __floats2half2_rn(xv.z, xv.w);
        uint2 u;
        u.x = *reinterpret_cast<uint32_t*>(&h01);
        u.y = *reinterpret_cast<uint32_t*>(&h23);
        *reinterpret_cast<uint2*>(g_xh + (size_t)t * D_DIM + d) = u;
#pragma unroll
        for (int e = 0; e < N_EXP; e++) {
            float4 wv = __ldg((const float4*)(gw + e * D_DIM + d));
            acc[e] += xv.x * wv.x + xv.y * wv.y + xv.z * wv.z + xv.w * wv.w;
        }
    }
#pragma unroll
    for (int e = 0; e < N_EXP; e++) {
#pragma unroll
        for (int o = 16; o > 0; o >>= 1) acc[e] += __shfl_xor_sync(0xffffffffu, acc[e], o);
    }
    if (lane == 0) {
        float lg[N_EXP], m = -1e30f;
#pragma unroll
        for (int e = 0; e < N_EXP; e++) { lg[e] = acc[e] + gb[e]; m = fmaxf(m, lg[e]); }
        float p[N_EXP], s = 0.f;
#pragma unroll
        for (int e = 0; e < N_EXP; e++) { p[e] = expf(lg[e] - m); s += p[e]; }
        int i1 = 0;
#pragma unroll
        for (int e = 1; e < N_EXP; e++) if (p[e] > p[i1]) i1 = e;
        int i2 = (i1 == 0) ? 1 : 0;
#pragma unroll
        for (int e = 0; e < N_EXP; e++) if (e != i1 && p[e] > p[i2]) i2 = e;
        float inv = 1.f / s;
        g_gval[2 * t]     = p[i1] * inv;
        g_gval[2 * t + 1] = p[i2] * inv;
        int q1 = atomicAdd(&g_cnt[i1], 1); g_list[i1 * CAPE + q1] = 2 * t;
        int q2 = atomicAdd(&g_cnt[i2], 1); g_list[i2 * CAPE + q2] = 2 * t + 1;
    }
}

// ---------------- grouped GEMM (WHICH=1: x@w1 +b1, relu -> g_h fp16)
// ----------------              (WHICH=2: h@w2 +b2, *gate -> g_part fp32)
template <int WHICH>
__global__ void __launch_bounds__(256, 2) moe_gemm_kernel(const float* __restrict__ bias) {
    constexpr int KDIM = (WHICH == 1) ? D_DIM : H_DIM;
    constexpr int NDIM = (WHICH == 1) ? H_DIM : O_DIM;
    constexpr int KT = KDIM / 32;

    const int e = blockIdx.z;
    const int ne = g_cnt[e];
    const int mbase = blockIdx.x * 128;
    if (mbase >= ne) return;
    const int nbase = blockIdx.y * 128;

    extern __shared__ char smem[];
    const uint32_t sb = smem_u32(smem);
    int*   slotsS = (int*)(smem + NSTAGE * STAGE_BYTES);
    float* biasS  = (float*)(smem + NSTAGE * STAGE_BYTES + 512);

    const int tid = threadIdx.x, lane = tid & 31, wid = tid >> 5;
    const int warp_m = wid >> 2, warp_n = wid & 3;

    if (tid < 128) {
        int grow = mbase + tid;
        slotsS[tid] = (grow < ne) ? __ldg(&g_list[e * CAPE + grow]) : -1;
        biasS[tid]  = __ldg(&bias[(size_t)e * NDIM + nbase + tid]);
    }
    __syncthreads();

    // per-thread cp.async source/dest (one A row + one B row, 2 chunks of 16B each)
    const int lrow = tid >> 1;
    const int j0 = (tid & 1) * 2;
    const int slotL = slotsS[lrow];
    uint32_t aSz = 16;
    const char* aSrc;
    if (slotL < 0) { aSrc = (const char*)g_xh; aSz = 0; }
    else if (WHICH == 1) aSrc = (const char*)(g_xh + (size_t)(slotL >> 1) * D_DIM);
    else                 aSrc = (const char*)(g_h + (size_t)slotL * H_DIM);
    aSrc += j0 * 16;
    const __half* wsrc = (WHICH == 1) ? (g_w1t + ((size_t)e * H_DIM + nbase) * D_DIM)
                                      : (g_w2t + ((size_t)e * O_DIM + nbase) * H_DIM);
    const char* bSrc = (const char*)(wsrc + (size_t)lrow * KDIM) + j0 * 16;
    const uint32_t aDst = sb + lrow * ROW_B + j0 * 16;
    const uint32_t bDst = sb + A_BYTES + lrow * ROW_B + j0 * 16;

#define ISSUE(kt_)                                                   \
    do {                                                             \
        uint32_t s_ = ((kt_) & 3) * STAGE_BYTES;                     \
        const char* as_ = aSrc + (size_t)(kt_) * 64;                 \
        const char* bs_ = bSrc + (size_t)(kt_) * 64;                 \
        CP16(aDst + s_,      as_,      aSz);                         \
        CP16(aDst + s_ + 16, as_ + 16, aSz);                         \
        CP16(bDst + s_,      bs_,      16u);                         \
        CP16(bDst + s_ + 16, bs_ + 16, 16u);                         \
    } while (0)

    ISSUE(0); CP_COMMIT();
    ISSUE(1); CP_COMMIT();
    ISSUE(2); CP_COMMIT();

    float acc[4][4][4];
#pragma unroll
    for (int a = 0; a < 4; a++)
#pragma unroll
        for (int b = 0; b < 4; b++)
#pragma unroll
            for (int c = 0; c < 4; c++) acc[a][b][c] = 0.f;

#pragma unroll 1
    for (int kt = 0; kt < KT; kt++) {
        CP_WAIT2();
        __syncthreads();
        if (kt + 3 < KT) ISSUE(kt + 3);
        CP_COMMIT();

        const uint32_t As = sb + (kt & 3) * STAGE_BYTES;
        const uint32_t Bs = As + A_BYTES;
#pragma unroll
        for (int ks = 0; ks < 2; ks++) {
            uint32_t bfr[8];
            const int grp = lane >> 3, l8 = lane & 7;
#pragma unroll
            for (int h = 0; h < 2; h++) {
                int nrow = warp_n * 32 + h * 16 + (grp >> 1) * 8 + l8;
                int chk = ks * 2 + (grp & 1);
                uint32_t addr = Bs + nrow * ROW_B + chk * 16;
                LDMX4(bfr[h * 4 + 0], bfr[h * 4 + 1], bfr[h * 4 + 2], bfr[h * 4 + 3], addr);
            }
#pragma unroll
            for (int mi = 0; mi < 4; mi++) {
                int arow = warp_m * 64 + mi * 16 + (lane & 15);
                int achk = ks * 2 + (lane >> 4);
                uint32_t addr = As + arow * ROW_B + achk * 16;
                uint32_t a0, a1, a2, a3;
                LDMX4(a0, a1, a2, a3, addr);
#pragma unroll
                for (int ni = 0; ni < 4; ni++) {
                    MMA16816(acc[mi][ni], a0, a1, a2, a3,
                             bfr[(ni >> 1) * 4 + (ni & 1) * 2],
                             bfr[(ni >> 1) * 4 + (ni & 1) * 2 + 1]);
                }
            }
        }
    }

    // epilogue
    const int gr = lane >> 2, gc = (lane & 3) * 2;
#pragma unroll
    for (int mi = 0; mi < 4; mi++) {
#pragma unroll
        for (int rh = 0; rh < 2; rh++) {
            int lr = warp_m * 64 + mi * 16 + rh * 8 + gr;
            int slot2 = slotsS[lr];
            if (slot2 < 0) continue;
            if (WHICH == 1) {
                __half* dst = g_h + (size_t)slot2 * H_DIM + nbase;
#pragma unroll
                for (int ni = 0; ni < 4; ni++) {
                    int lc = warp_n * 32 + ni * 8 + gc;
                    float v0 = fmaxf(acc[mi][ni][rh * 2 + 0] + biasS[lc], 0.f);
                    float v1 = fmaxf(acc[mi][ni][rh * 2 + 1] + biasS[lc + 1], 0.f);
                    *(__half2*)(dst + lc) = __floats2half2_rn(v0, v1);
                }
            } else {
                float gv = __ldg(&g_gval[slot2]);
                float* dst = g_part + (size_t)slot2 * O_DIM + nbase;
#pragma unroll
                for (int ni = 0; ni < 4; ni++) {
                    int lc = warp_n * 32 + ni * 8 + gc;
                    float2 o;
                    o.x = (acc[mi][ni][rh * 2 + 0] + biasS[lc]) * gv;
                    o.y = (acc[mi][ni][rh * 2 + 1] + biasS[lc + 1]) * gv;
                    *(float2*)(dst + lc) = o;
                }
            }
        }
    }
#undef ISSUE
}

// ---------------- combine: out[t] = part[2t] + part[2t+1] ----------------
__global__ void __launch_bounds__(256) combine_kernel(float* __restrict__ out) {
    int i = blockIdx.x * 256 + threadIdx.x;   // over T_TOK * O_DIM / 4
    int t = i >> 8, q = i & 255;
    const float4 a = *((const float4*)(g_part + (size_t)(2 * t) * O_DIM) + q);
    const float4 b = *((const float4*)(g_part + (size_t)(2 * t + 1) * O_DIM) + q);
    ((float4*)(out + (size_t)t * O_DIM))[q] =
        make_float4(a.x + b.x, a.y + b.y, a.z + b.z, a.w + b.w);
}

// ---------------- launcher ----------------
extern "C" void kernel_launch(void* const* d_in, const int* in_sizes, int n_in,
                              void* d_out, int out_size) {
    const float* x  = (const float*)d_in[0];
    const float* gw = (const float*)d_in[1];
    const float* gb = (const float*)d_in[2];
    const float* w1 = (const float*)d_in[3];
    const float* b1 = (const float*)d_in[4];
    const float* w2 = (const float*)d_in[5];
    const float* b2 = (const float*)d_in[6];
    float* out = (float*)d_out;

    cudaFuncSetAttribute(moe_gemm_kernel<1>, cudaFuncAttributeMaxDynamicSharedMemorySize, SMEM_GEMM);
    cudaFuncSetAttribute(moe_gemm_kernel<2>, cudaFuncAttributeMaxDynamicSharedMemorySize, SMEM_GEMM);

    // order chosen so gemm1 is the 4th kernel launch (profiler capture slot)
    transpose_w_kernel<<<dim3(H_DIM / 32, D_DIM / 32, N_EXP), dim3(8, 32)>>>(w1, D_DIM, H_DIM, 0, 1);
    transpose_w_kernel<<<dim3(O_DIM / 32, H_DIM / 32, N_EXP), dim3(8, 32)>>>(w2, H_DIM, O_DIM, 1, 0);
    gate_kernel<<<T_TOK / 8, 256>>>(x, gw, gb);
    moe_gemm_kernel<1><<<dim3(CAPE / 128, H_DIM / 128, N_EXP), 256, SMEM_GEMM>>>(b1);
    moe_gemm_kernel<2><<<dim3(CAPE / 128, O_DIM / 128, N_EXP), 256, SMEM_GEMM>>>(b2);
    combine_kernel<<<(T_TOK * O_DIM / 4) / 256, 256>>>(out);
}

// round 9
// speedup vs baseline: 1.0186x; 1.0042x over previous
#include <cuda_runtime.h>
#include <cuda_fp16.h>
#include <cstdint>

// ---------------- problem dims ----------------
#define T_TOK 8192
#define D_DIM 1024
#define H_DIM 2048
#define O_DIM 1024
#define N_EXP 8
#define SLOTS 16384   // T_TOK * 2
#define CAPE  8192    // max rows per expert

// ---------------- scratch (device globals; no allocation allowed) ----------------
__device__ __half g_xh[(size_t)T_TOK * D_DIM];            // x in fp16
__device__ __half g_w1t[(size_t)N_EXP * H_DIM * D_DIM];   // w1^T  [E][H][D]
__device__ __half g_w2t[(size_t)N_EXP * O_DIM * H_DIM];   // w2^T  [E][O][H]
__device__ __half g_h[(size_t)SLOTS * H_DIM];             // hidden per slot
__device__ float  g_part[(size_t)SLOTS * O_DIM];          // partial out per slot
__device__ int    g_list[N_EXP * CAPE];                   // slot ids per expert
__device__ float  g_gval[SLOTS];                          // gate value per slot
__device__ int    g_cnt[N_EXP];

// ---------------- helpers ----------------
__device__ __forceinline__ uint32_t smem_u32(const void* p) {
    uint32_t a;
    asm("{ .reg .u64 t; cvta.to.shared.u64 t, %1; cvt.u32.u64 %0, t; }" : "=r"(a) : "l"(p));
    return a;
}
#define CP16(d, s, sz) \
    asm volatile("cp.async.cg.shared.global [%0], [%1], 16, %2;" :: "r"(d), "l"(s), "r"(sz))
#define CP_COMMIT() asm volatile("cp.async.commit_group;")
#define CP_WAIT2()  asm volatile("cp.async.wait_group 2;")
#define LDMX4(r0, r1, r2, r3, addr)                                            \
    asm volatile("ldmatrix.sync.aligned.m8n8.x4.shared.b16 {%0,%1,%2,%3}, [%4];" \
        : "=r"(r0), "=r"(r1), "=r"(r2), "=r"(r3) : "r"(addr))
#define MMA16816(d, a0, a1, a2, a3, b0, b1)                                    \
    asm volatile("mma.sync.aligned.m16n8k16.row.col.f32.f16.f16.f32 "          \
        "{%0,%1,%2,%3}, {%4,%5,%6,%7}, {%8,%9}, {%0,%1,%2,%3};"                \
        : "+f"((d)[0]), "+f"((d)[1]), "+f"((d)[2]), "+f"((d)[3])               \
        : "r"(a0), "r"(a1), "r"(a2), "r"(a3), "r"(b0), "r"(b1))

// smem tile layout: per stage A[128][40 halfs] (80B rows) + B[128][40]
#define ROW_B 80
#define A_BYTES (128 * ROW_B)          // 10240
#define STAGE_BYTES (2 * A_BYTES)      // 20480
#define NSTAGE 4
#define SMEM_GEMM (NSTAGE * STAGE_BYTES + 512 + 512)   // tiles + slots + bias = 82944

// ---------------- kernel 1: weight transpose + fp16 convert (vectorized) ----------
// in: [E][R][C] fp32 -> out: [E][C][R] fp16; zflag: also zero g_cnt (block 0)
__global__ void __launch_bounds__(256) transpose_w_kernel(const float* __restrict__ in,
                                                          int R, int C, int which, int zflag) {
    __shared__ float tile[32][33];
    if (zflag && blockIdx.x == 0 && blockIdx.y == 0 && blockIdx.z == 0 && threadIdx.x < N_EXP &&
        threadIdx.y == 0)
        g_cnt[threadIdx.x] = 0;
    const int e = blockIdx.z;
    const size_t base = (size_t)e * R * C;
    const int c0 = blockIdx.x * 32, r0 = blockIdx.y * 32;
    const int tx = threadIdx.x, ty = threadIdx.y;   // blockDim = (8, 32)
    float4 v = *(const float4*)(in + base + (size_t)(r0 + ty) * C + c0 + 4 * tx);
    tile[ty][4 * tx + 0] = v.x;
    tile[ty][4 * tx + 1] = v.y;
    tile[ty][4 * tx + 2] = v.z;
    tile[ty][4 * tx + 3] = v.w;
    __syncthreads();
    __half* out = which ? g_w2t : g_w1t;
    float f0 = tile[4 * tx + 0][ty];
    float f1 = tile[4 * tx + 1][ty];
    float f2 = tile[4 * tx + 2][ty];
    float f3 = tile[4 * tx + 3][ty];
    __half2 h01 = __floats2half2_rn(f0, f1);
    __half2 h23 = __floats2half2_rn(f2, f3);
    uint2 u;
    u.x = *reinterpret_cast<uint32_t*>(&h01);
    u.y = *reinterpret_cast<uint32_t*>(&h23);
    *reinterpret_cast<uint2*>(out + base + (size_t)(c0 + ty) * R + r0 + 4 * tx) = u;
}

// ---------------- kernel 2: gate + x->fp16 (vectorized) ----------------
__global__ void __launch_bounds__(256) gate_kernel(const float* __restrict__ x,
                                                   const float* __restrict__ gw,
                                                   const float* __restrict__ gb) {
    const int warp = threadIdx.x >> 5, lane = threadIdx.x & 31;
    const int t = blockIdx.x * 8 + warp;
    const float* xr = x + (size_t)t * D_DIM;
    float acc[N_EXP];
#pragma unroll
    for (int e = 0; e < N_EXP; e++) acc[e] = 0.f;
#pragma unroll 1
    for (int d = lane * 4; d < D_DIM; d += 128) {
        float4 xv = *(const float4*)(xr + d);
        __half2 h01 = __floats2half2_rn(xv.x, xv.y);
        __half2 h23 = __floats2half2_rn(xv.z, xv.w);
        uint2 u;
        u.x = *reinterpret_cast<uint32_t*>(&h01);
        u.y = *reinterpret_cast<uint32_t*>(&h23);
        *reinterpret_cast<uint2*>(g_xh + (size_t)t * D_DIM + d) = u;
#pragma unroll
        for (int e = 0; e < N_EXP; e++) {
            float4 wv = __ldg((const float4*)(gw + e * D_DIM + d));
            acc[e] += xv.x * wv.x + xv.y * wv.y + xv.z * wv.z + xv.w * wv.w;
        }
    }
#pragma unroll
    for (int e = 0; e < N_EXP; e++) {
#pragma unroll
        for (int o = 16; o > 0; o >>= 1) acc[e] += __shfl_xor_sync(0xffffffffu, acc[e], o);
    }
    if (lane == 0) {
        float lg[N_EXP], m = -1e30f;
#pragma unroll
        for (int e = 0; e < N_EXP; e++) { lg[e] = acc[e] + gb[e]; m = fmaxf(m, lg[e]); }
        float p[N_EXP], s = 0.f;
#pragma unroll
        for (int e = 0; e < N_EXP; e++) { p[e] = expf(lg[e] - m); s += p[e]; }
        int i1 = 0;
#pragma unroll
        for (int e = 1; e < N_EXP; e++) if (p[e] > p[i1]) i1 = e;
        int i2 = (i1 == 0) ? 1 : 0;
#pragma unroll
        for (int e = 0; e < N_EXP; e++) if (e != i1 && p[e] > p[i2]) i2 = e;
        float inv = 1.f / s;
        g_gval[2 * t]     = p[i1] * inv;
        g_gval[2 * t + 1] = p[i2] * inv;
        int q1 = atomicAdd(&g_cnt[i1], 1); g_list[i1 * CAPE + q1] = 2 * t;
        int q2 = atomicAdd(&g_cnt[i2], 1); g_list[i2 * CAPE + q2] = 2 * t + 1;
    }
}

// ---------------- grouped GEMM (WHICH=1: x@w1 +b1, relu -> g_h fp16)
// ----------------              (WHICH=2: h@w2 +b2, *gate -> g_part fp32)
template <int WHICH>
__global__ void __launch_bounds__(256, 2) moe_gemm_kernel(const float* __restrict__ bias) {
    constexpr int KDIM = (WHICH == 1) ? D_DIM : H_DIM;
    constexpr int NDIM = (WHICH == 1) ? H_DIM : O_DIM;
    constexpr int KT = KDIM / 32;

    const int e = blockIdx.z;
    const int ne = g_cnt[e];
    const int mbase = blockIdx.x * 128;
    if (mbase >= ne) return;
    const int nbase = blockIdx.y * 128;

    extern __shared__ char smem[];
    const uint32_t sb = smem_u32(smem);
    int*   slotsS = (int*)(smem + NSTAGE * STAGE_BYTES);
    float* biasS  = (float*)(smem + NSTAGE * STAGE_BYTES + 512);

    const int tid = threadIdx.x, lane = tid & 31, wid = tid >> 5;
    const int warp_m = wid >> 2, warp_n = wid & 3;

    if (tid < 128) {
        int grow = mbase + tid;
        slotsS[tid] = (grow < ne) ? __ldg(&g_list[e * CAPE + grow]) : -1;
        biasS[tid]  = __ldg(&bias[(size_t)e * NDIM + nbase + tid]);
    }
    __syncthreads();

    // per-thread cp.async source/dest (one A row + one B row, 2 chunks of 16B each)
    const int lrow = tid >> 1;
    const int j0 = (tid & 1) * 2;
    const int slotL = slotsS[lrow];
    uint32_t aSz = 16;
    const char* aSrc;
    if (slotL < 0) { aSrc = (const char*)g_xh; aSz = 0; }
    else if (WHICH == 1) aSrc = (const char*)(g_xh + (size_t)(slotL >> 1) * D_DIM);
    else                 aSrc = (const char*)(g_h + (size_t)slotL * H_DIM);
    aSrc += j0 * 16;
    const __half* wsrc = (WHICH == 1) ? (g_w1t + ((size_t)e * H_DIM + nbase) * D_DIM)
                                      : (g_w2t + ((size_t)e * O_DIM + nbase) * H_DIM);
    const char* bSrc = (const char*)(wsrc + (size_t)lrow * KDIM) + j0 * 16;
    const uint32_t aDst = sb + lrow * ROW_B + j0 * 16;
    const uint32_t bDst = sb + A_BYTES + lrow * ROW_B + j0 * 16;

#define ISSUE(kt_)                                                   \
    do {                                                             \
        uint32_t s_ = ((kt_) & 3) * STAGE_BYTES;                     \
        const char* as_ = aSrc + (size_t)(kt_) * 64;                 \
        const char* bs_ = bSrc + (size_t)(kt_) * 64;                 \
        CP16(aDst + s_,      as_,      aSz);                         \
        CP16(aDst + s_ + 16, as_ + 16, aSz);                         \
        CP16(bDst + s_,      bs_,      16u);                         \
        CP16(bDst + s_ + 16, bs_ + 16, 16u);                         \
    } while (0)

    ISSUE(0); CP_COMMIT();
    ISSUE(1); CP_COMMIT();
    ISSUE(2); CP_COMMIT();

    float acc[4][4][4];
#pragma unroll
    for (int a = 0; a < 4; a++)
#pragma unroll
        for (int b = 0; b < 4; b++)
#pragma unroll
            for (int c = 0; c < 4; c++) acc[a][b][c] = 0.f;

#pragma unroll 1
    for (int kt = 0; kt < KT; kt++) {
        CP_WAIT2();
        __syncthreads();
        if (kt + 3 < KT) ISSUE(kt + 3);
        CP_COMMIT();

        const uint32_t As = sb + (kt & 3) * STAGE_BYTES;
        const uint32_t Bs = As + A_BYTES;
#pragma unroll
        for (int ks = 0; ks < 2; ks++) {
            uint32_t bfr[8];
            const int grp = lane >> 3, l8 = lane & 7;
#pragma unroll
            for (int h = 0; h < 2; h++) {
                int nrow = warp_n * 32 + h * 16 + (grp >> 1) * 8 + l8;
                int chk = ks * 2 + (grp & 1);
                uint32_t addr = Bs + nrow * ROW_B + chk * 16;
                LDMX4(bfr[h * 4 + 0], bfr[h * 4 + 1], bfr[h * 4 + 2], bfr[h * 4 + 3], addr);
            }
            // A-fragment software pipeline: LDSM for mi+1 issues before MMAs of mi,
            // hiding the ~29cyc shared-mem latency behind 4 MMAs of tensor work.
            const int arow_lane = lane & 15;
            const int achk = ks * 2 + (lane >> 4);
            uint32_t aCur0, aCur1, aCur2, aCur3;
            {
                uint32_t addr = As + (warp_m * 64 + 0 * 16 + arow_lane) * ROW_B + achk * 16;
                LDMX4(aCur0, aCur1, aCur2, aCur3, addr);
            }
#pragma unroll
            for (int mi = 0; mi < 4; mi++) {
                uint32_t aNxt0, aNxt1, aNxt2, aNxt3;
                if (mi < 3) {
                    uint32_t addr = As + (warp_m * 64 + (mi + 1) * 16 + arow_lane) * ROW_B + achk * 16;
                    LDMX4(aNxt0, aNxt1, aNxt2, aNxt3, addr);
                }
#pragma unroll
                for (int ni = 0; ni < 4; ni++) {
                    MMA16816(acc[mi][ni], aCur0, aCur1, aCur2, aCur3,
                             bfr[(ni >> 1) * 4 + (ni & 1) * 2],
                             bfr[(ni >> 1) * 4 + (ni & 1) * 2 + 1]);
                }
                if (mi < 3) { aCur0 = aNxt0; aCur1 = aNxt1; aCur2 = aNxt2; aCur3 = aNxt3; }
            }
        }
    }

    // epilogue
    const int gr = lane >> 2, gc = (lane & 3) * 2;
#pragma unroll
    for (int mi = 0; mi < 4; mi++) {
#pragma unroll
        for (int rh = 0; rh < 2; rh++) {
            int lr = warp_m * 64 + mi * 16 + rh * 8 + gr;
            int slot2 = slotsS[lr];
            if (slot2 < 0) continue;
            if (WHICH == 1) {
                __half* dst = g_h + (size_t)slot2 * H_DIM + nbase;
#pragma unroll
                for (int ni = 0; ni < 4; ni++) {
                    int lc = warp_n * 32 + ni * 8 + gc;
                    float v0 = fmaxf(acc[mi][ni][rh * 2 + 0] + biasS[lc], 0.f);
                    float v1 = fmaxf(acc[mi][ni][rh * 2 + 1] + biasS[lc + 1], 0.f);
                    *(__half2*)(dst + lc) = __floats2half2_rn(v0, v1);
                }
            } else {
                float gv = __ldg(&g_gval[slot2]);
                float* dst = g_part + (size_t)slot2 * O_DIM + nbase;
#pragma unroll
                for (int ni = 0; ni < 4; ni++) {
                    int lc = warp_n * 32 + ni * 8 + gc;
                    float2 o;
                    o.x = (acc[mi][ni][rh * 2 + 0] + biasS[lc]) * gv;
                    o.y = (acc[mi][ni][rh * 2 + 1] + biasS[lc + 1]) * gv;
                    *(float2*)(dst + lc) = o;
                }
            }
        }
    }
#undef ISSUE
}

// ---------------- combine: out[t] = part[2t] + part[2t+1] ----------------
__global__ void __launch_bounds__(256) combine_kernel(float* __restrict__ out) {
    int i = blockIdx.x * 256 + threadIdx.x;   // over T_TOK * O_DIM / 4
    int t = i >> 8, q = i & 255;
    const float4 a = *((const float4*)(g_part + (size_t)(2 * t) * O_DIM) + q);
    const float4 b = *((const float4*)(g_part + (size_t)(2 * t + 1) * O_DIM) + q);
    ((float4*)(out + (size_t)t * O_DIM))[q] =
        make_float4(a.x + b.x, a.y + b.y, a.z + b.z, a.w + b.w);
}

// ---------------- launcher ----------------
extern "C" void kernel_launch(void* const* d_in, const int* in_sizes, int n_in,
                              void* d_out, int out_size) {
    const float* x  = (const float*)d_in[0];
    const float* gw = (const float*)d_in[1];
    const float* gb = (const float*)d_in[2];
    const float* w1 = (const float*)d_in[3];
    const float* b1 = (const float*)d_in[4];
    const float* w2 = (const float*)d_in[5];
    const float* b2 = (const float*)d_in[6];
    float* out = (float*)d_out;

    cudaFuncSetAttribute(moe_gemm_kernel<1>, cudaFuncAttributeMaxDynamicSharedMemorySize, SMEM_GEMM);
    cudaFuncSetAttribute(moe_gemm_kernel<2>, cudaFuncAttributeMaxDynamicSharedMemorySize, SMEM_GEMM);

    // order chosen so gemm1 is the 4th kernel launch (profiler capture slot)
    transpose_w_kernel<<<dim3(H_DIM / 32, D_DIM / 32, N_EXP), dim3(8, 32)>>>(w1, D_DIM, H_DIM, 0, 1);
    transpose_w_kernel<<<dim3(O_DIM / 32, H_DIM / 32, N_EXP), dim3(8, 32)>>>(w2, H_DIM, O_DIM, 1, 0);
    gate_kernel<<<T_TOK / 8, 256>>>(x, gw, gb);
    moe_gemm_kernel<1><<<dim3(CAPE / 128, H_DIM / 128, N_EXP), 256, SMEM_GEMM>>>(b1);
    moe_gemm_kernel<2><<<dim3(CAPE / 128, O_DIM / 128, N_EXP), 256, SMEM_GEMM>>>(b2);
    combine_kernel<<<(T_TOK * O_DIM / 4) / 256, 256>>>(out);
}